// round 10
// baseline (speedup 1.0000x reference)
#include <cuda_runtime.h>
#include <math.h>

// ---------------------------------------------------------------------------
// YoloLoss, single fused kernel, v3:
//   - pred streamed block-wise into shared memory with coalesced float4 loads
//     (stream-rate DRAM instead of 120B-strided scattered LDG.64)
//   - noobj lanes touch no global memory after staging
//   - tbox/tcls remain scattered + gated on obj (sector-level savings)
//   - block partials -> global double atomics -> last-block finalize
// ---------------------------------------------------------------------------

#define S_INV (1.0f / 14.0f)
#define CPB   256                 // cells per block (== blockDim.x)

// acc[0]=n_obj, [1]=cls, [2]=noobj, [3]=reg, [4]=conf. Zero-initialized; the
// finalizing block restores them to zero (deterministic across graph replays).
__device__ double g_acc[5];
__device__ unsigned int g_done;

__device__ __forceinline__ float iou_xyxy(
    float x1, float y1, float x2, float y2,
    float tx1, float ty1, float tx2, float ty2)
{
    float lx = fmaxf(x1, tx1), ly = fmaxf(y1, ty1);
    float rx = fminf(x2, tx2), ry = fminf(y2, ty2);
    float w = fmaxf(rx - lx, 0.0f), h = fmaxf(ry - ly, 0.0f);
    float inter = w * h;
    float a1 = (x2 - x1) * (y2 - y1);
    float a2 = (tx2 - tx1) * (ty2 - ty1);
    return inter / (a1 + a2 - inter);
}

__global__ void __launch_bounds__(256)
yolo_fused(const float* __restrict__ pred,
           const float* __restrict__ tbox,
           const float* __restrict__ tcls,
           const void*  __restrict__ objp,
           float* __restrict__ out,
           int ncells, float Nf, int nblocks)
{
    __shared__ __align__(16) float sp[CPB * 30];   // 30720 B staged pred

    int tid = threadIdx.x;
    int cb  = blockIdx.x * CPB;                    // first cell of this block
    int ncell_blk = min(CPB, ncells - cb);

    // ---- stage pred: coalesced float4 stream (issue these LDGs first) -----
    // block covers floats [cb*30, cb*30 + ncell_blk*30); cb*30 is 16B-aligned
    {
        const float4* gp = (const float4*)(pred + (size_t)cb * 30);
        int nf = ncell_blk * 30;
        int n4 = nf >> 2;                          // 1920 for a full block
        #pragma unroll
        for (int k = 0; k < 8; k++) {
            int idx = tid + k * 256;
            if (idx < n4) ((float4*)sp)[idx] = gp[idx];
        }
        int rem = nf & 3;                          // 0 or 2 (30*cells is even)
        if (rem && tid == 0)
            ((float2*)sp)[n4 * 2] =
                ((const float2*)(pred + (size_t)cb * 30))[n4 * 2];
    }

    // ---- dtype detection from 4KB prefix (one uint4 per thread) -----------
    //   float32 1.0f = 00 00 80 3F : byte with bits above 1     -> gt1
    //   uint8   0/1  : nonzero byte at offset %4 != 0           -> off4
    //   int32   0/1  : nonzero only at byte offset %4 == 0      -> neither
    uint4 w = ((const uint4*)objp)[tid];
    unsigned v_all = w.x | w.y | w.z | w.w;
    int gt1  = __syncthreads_or((v_all & 0xFEFEFEFEu) != 0);
    int off4 = __syncthreads_or((v_all & 0xFFFFFF00u) != 0);
    int dt = gt1 ? 2 : (off4 ? 1 : 0);             // 2=f32, 1=u8, 0=i32

    // ---- obj value for this thread's cell ---------------------------------
    int i = cb + tid;
    bool act = (tid < ncell_blk);
    float obj = 0.0f;
    if (act) {
        if (dt == 2)      obj = ((const float*)objp)[i];
        else if (dt == 1) obj = (float)((const unsigned char*)objp)[i];
        else              obj = (float)((const int*)objp)[i];
    }

    __syncthreads();                               // staged pred visible

    // ---- process one cell from smem ---------------------------------------
    float v_nobj = 0.0f, v_cls = 0.0f, v_noobj = 0.0f, v_reg = 0.0f, v_conf = 0.0f;

    const float* p = sp + tid * 30;                // 120B stride: conflict-free LDS.64
    if (act) {
        float2 a0 = *(const float2*)(p + 0);
        float2 a1 = *(const float2*)(p + 2);
        float2 a2 = *(const float2*)(p + 4);
        float2 a3 = *(const float2*)(p + 6);
        float2 a4 = *(const float2*)(p + 8);

        if (obj > 0.5f) {
            v_nobj = 1.0f;

            float4 tb = ((const float4*)tbox)[i];
            float tcx = tb.x * S_INV, tcy = tb.y * S_INV;
            float tx1 = tcx - 0.5f * tb.z, ty1 = tcy - 0.5f * tb.w;
            float tx2 = tcx + 0.5f * tb.z, ty2 = tcy + 0.5f * tb.w;

            float b1x = a0.x, b1y = a0.y, b1w = a1.x, b1h = a1.y, b1c = a2.x;
            float b2x = a2.y, b2y = a3.x, b2w = a3.y, b2h = a4.x, b2c = a4.y;

            float c1x = b1x * S_INV, c1y = b1y * S_INV;
            float c2x = b2x * S_INV, c2y = b2y * S_INV;

            float iou1 = iou_xyxy(c1x - 0.5f * b1w, c1y - 0.5f * b1h,
                                  c1x + 0.5f * b1w, c1y + 0.5f * b1h,
                                  tx1, ty1, tx2, ty2);
            float iou2 = iou_xyxy(c2x - 0.5f * b2w, c2y - 0.5f * b2h,
                                  c2x + 0.5f * b2w, c2y + 0.5f * b2h,
                                  tx1, ty1, tx2, ty2);

            bool take1 = (iou1 >= iou2);
            float bx = take1 ? b1x : b2x;
            float by = take1 ? b1y : b2y;
            float bw = take1 ? b1w : b2w;
            float bh = take1 ? b1h : b2h;
            float bc = take1 ? b1c : b2c;
            float biou = take1 ? iou1 : iou2;

            float dx = bx - tb.x;
            float dy = by - tb.y;
            float dw = sqrtf(bw) - sqrtf(tb.z);
            float dh = sqrtf(bh) - sqrtf(tb.w);
            v_reg = dx * dx + dy * dy + dw * dw + dh * dh;

            float dc = bc - biou;
            v_conf = dc * dc;

            // class loss: pred-cls from smem, target-cls gated scattered load
            const float2* pc = (const float2*)(p + 10);
            const float4* tc = (const float4*)(tcls + (size_t)i * 20);
            float s = 0.0f;
            #pragma unroll
            for (int j = 0; j < 5; j++) {
                float4 t  = tc[j];
                float2 c0 = pc[2 * j];
                float2 c1 = pc[2 * j + 1];
                float d0 = c0.x - t.x, d1 = c0.y - t.y;
                float d2 = c1.x - t.z, d3 = c1.y - t.w;
                s += d0 * d0 + d1 * d1 + d2 * d2 + d3 * d3;
            }
            v_cls = s;
        } else {
            v_noobj = a0.x * a0.x + a0.y * a0.y + a1.x * a1.x + a1.y * a1.y
                    + a2.x * a2.x + a2.y * a2.y + a3.x * a3.x + a3.y * a3.y
                    + a4.x * a4.x + a4.y * a4.y;
        }
    }

    // ---- block reduction ---------------------------------------------------
    const unsigned m = 0xffffffffu;
    #pragma unroll
    for (int off = 16; off > 0; off >>= 1) {
        v_nobj  += __shfl_down_sync(m, v_nobj,  off);
        v_cls   += __shfl_down_sync(m, v_cls,   off);
        v_noobj += __shfl_down_sync(m, v_noobj, off);
        v_reg   += __shfl_down_sync(m, v_reg,   off);
        v_conf  += __shfl_down_sync(m, v_conf,  off);
    }

    __shared__ double sacc[5];
    if (tid < 5) sacc[tid] = 0.0;
    __syncthreads();
    if ((tid & 31) == 0) {
        atomicAdd(&sacc[0], (double)v_nobj);
        atomicAdd(&sacc[1], (double)v_cls);
        atomicAdd(&sacc[2], (double)v_noobj);
        atomicAdd(&sacc[3], (double)v_reg);
        atomicAdd(&sacc[4], (double)v_conf);
    }
    __syncthreads();
    if (tid < 5)
        atomicAdd(&g_acc[tid], sacc[tid]);

    // ---- last-block finalize ----------------------------------------------
    __threadfence();
    __shared__ unsigned int ticket;
    if (tid == 0) ticket = atomicAdd(&g_done, 1u);
    __syncthreads();
    if (ticket == (unsigned)(nblocks - 1) && tid == 0) {
        __threadfence();
        double n_obj   = g_acc[0];
        double n_noobj = (double)ncells - n_obj;
        double cls   = g_acc[1] / (double)Nf;
        double noobj = 0.5 * g_acc[2] / n_noobj;
        double reg   = 5.0 * g_acc[3] / n_obj;
        double conf  = g_acc[4] / n_obj;
        out[0] = (float)(reg + conf + noobj + cls);
        out[1] = (float)reg;
        out[2] = (float)conf;
        out[3] = (float)noobj;
        out[4] = (float)cls;
        g_acc[0] = 0.0; g_acc[1] = 0.0; g_acc[2] = 0.0;
        g_acc[3] = 0.0; g_acc[4] = 0.0;
        g_done = 0u;
    }
}

extern "C" void kernel_launch(void* const* d_in, const int* in_sizes, int n_in,
                              void* d_out, int out_size)
{
    const float* pred = (const float*)d_in[0];
    const float* tbox = (const float*)d_in[1];
    const float* tcls = (const float*)d_in[2];
    const void*  objp = d_in[3];

    int ncells = in_sizes[1] / 4;              // target_boxes: 4 floats/cell
    int nbatch = in_sizes[0] / (14 * 14 * 30);
    int nblocks = (ncells + CPB - 1) / CPB;    // 3136 for reference shape

    yolo_fused<<<nblocks, CPB>>>(pred, tbox, tcls, objp,
                                 (float*)d_out, ncells, (float)nbatch, nblocks);
}